// round 15
// baseline (speedup 1.0000x reference)
#include <cuda_runtime.h>
#include <cuda_fp16.h>
#include <cstdint>
#include <cmath>

// ---------------- problem constants ----------------
#define BATCH   4
#define SEQ     2048
#define DMODEL  1024
#define NHEADS  16
#define HEADDIM 64
#define DFF     4096
#define MTOK    (BATCH*SEQ)          // 8192 rows
#define NQKV    (3*DMODEL)           // fused QKV width

// ---------------- scratch (device globals, no runtime alloc) ----------------
__device__ __align__(256) __half g_xn [MTOK*DMODEL];
__device__ __align__(256) __half g_qkv[MTOK*NQKV];       // [row][q|k|v]
__device__ __align__(256) __half g_ctx[MTOK*DMODEL];
__device__ __align__(256) float  g_x  [MTOK*DMODEL];
__device__ __align__(256) __half g_yn [MTOK*DMODEL];
__device__ __align__(256) __half g_h1 [MTOK*DFF];
// transposed weights: [N,K] K-major, fp16
__device__ __align__(256) __half g_wqkv[NQKV*DMODEL];
__device__ __align__(256) __half g_wo[DMODEL*DMODEL];
__device__ __align__(256) __half g_w1[DMODEL*DFF];
__device__ __align__(256) __half g_w2[DFF*DMODEL];
__device__ float g_bqkv[NQKV];
__device__ float g_bias_tab[NHEADS*4096];   // [h][ (k-q)+2047 ], pre-scaled by log2(e)

// ================= warp-MMA helpers (sm_80+ PTX) =================
__device__ __forceinline__ uint32_t smem_u32(const void* p) {
    return (uint32_t)__cvta_generic_to_shared(p);
}
__device__ __forceinline__ void cp_async16(uint32_t dst, const void* src) {
    asm volatile("cp.async.cg.shared.global [%0], [%1], 16;" :: "r"(dst), "l"(src));
}
__device__ __forceinline__ void cp_commit() {
    asm volatile("cp.async.commit_group;");
}
template<int N>
__device__ __forceinline__ void cp_wait() {
    asm volatile("cp.async.wait_group %0;" :: "n"(N));
}
__device__ __forceinline__ void ldsm_x4(uint32_t (&r)[4], uint32_t addr) {
    asm volatile("ldmatrix.sync.aligned.m8n8.x4.shared.b16 {%0,%1,%2,%3}, [%4];"
                 : "=r"(r[0]), "=r"(r[1]), "=r"(r[2]), "=r"(r[3]) : "r"(addr));
}
__device__ __forceinline__ void ldsm_x4_t(uint32_t (&r)[4], uint32_t addr) {
    asm volatile("ldmatrix.sync.aligned.m8n8.x4.trans.shared.b16 {%0,%1,%2,%3}, [%4];"
                 : "=r"(r[0]), "=r"(r[1]), "=r"(r[2]), "=r"(r[3]) : "r"(addr));
}
__device__ __forceinline__ void mma16816(float (&d)[4], const uint32_t (&a)[4],
                                         uint32_t b0, uint32_t b1) {
    asm volatile(
        "mma.sync.aligned.m16n8k16.row.col.f32.f16.f16.f32 "
        "{%0,%1,%2,%3}, {%4,%5,%6,%7}, {%8,%9}, {%0,%1,%2,%3};"
        : "+f"(d[0]), "+f"(d[1]), "+f"(d[2]), "+f"(d[3])
        : "r"(a[0]), "r"(a[1]), "r"(a[2]), "r"(a[3]), "r"(b0), "r"(b1));
}
// fp16-accumulator variant: d0 = {row, col:col+1}, d1 = {row+8, col:col+1}
__device__ __forceinline__ void mma16816_h(uint32_t (&d)[2], const uint32_t (&a)[4],
                                           uint32_t b0, uint32_t b1) {
    asm volatile(
        "mma.sync.aligned.m16n8k16.row.col.f16.f16.f16.f16 "
        "{%0,%1}, {%2,%3,%4,%5}, {%6,%7}, {%0,%1};"
        : "+r"(d[0]), "+r"(d[1])
        : "r"(a[0]), "r"(a[1]), "r"(a[2]), "r"(a[3]), "r"(b0), "r"(b1));
}
__device__ __forceinline__ uint32_t pack_f16x2(float lo, float hi) {
    __half2 t;
    t.x = __float2half(lo);
    t.y = __float2half(hi);
    return *reinterpret_cast<uint32_t*>(&t);
}
// cvt.rn.f16x2.f32 d, hi, lo  -> low half = lo
__device__ __forceinline__ uint32_t cvt_f16x2(float lo, float hi) {
    uint32_t d;
    asm("cvt.rn.f16x2.f32 %0, %1, %2;" : "=r"(d) : "f"(hi), "f"(lo));
    return d;
}
__device__ __forceinline__ uint32_t ex2_f16x2(uint32_t x) {
    uint32_t d;
    asm("ex2.approx.f16x2 %0, %1;" : "=r"(d) : "r"(x));
    return d;
}
__device__ __forceinline__ uint32_t hmul2_u32(uint32_t a, uint32_t b) {
    uint32_t d;
    asm("mul.f16x2 %0, %1, %2;" : "=r"(d) : "r"(a), "r"(b));
    return d;
}

// ---------------- LayerNorm: one block per row, single-pass reduction ----------------
__global__ __launch_bounds__(256)
void ln_kernel(const float* __restrict__ X, const float* __restrict__ gw,
               const float* __restrict__ bw, __half* __restrict__ Y)
{
    __shared__ float red[8][2];
    const int row = blockIdx.x;
    const int tid = threadIdx.x;
    const int lane = tid & 31, warp = tid >> 5;
    const float* xr = X + (size_t)row * DMODEL;

    float4 v = *(const float4*)&xr[tid * 4];
    float s  = v.x + v.y + v.z + v.w;
    float sq = fmaf(v.x, v.x, fmaf(v.y, v.y, fmaf(v.z, v.z, v.w * v.w)));
    #pragma unroll
    for (int o = 16; o; o >>= 1) {
        s  += __shfl_xor_sync(0xffffffffu, s,  o);
        sq += __shfl_xor_sync(0xffffffffu, sq, o);
    }
    if (lane == 0) { red[warp][0] = s; red[warp][1] = sq; }
    __syncthreads();
    float S = 0.f, SQ = 0.f;
    #pragma unroll
    for (int i = 0; i < 8; i++) { S += red[i][0]; SQ += red[i][1]; }
    float mu  = S * (1.0f / DMODEL);
    float var = SQ * (1.0f / DMODEL) - mu * mu;
    float rs  = rsqrtf(var + 1e-6f);

    float4 gv = *(const float4*)&gw[tid * 4];
    float4 bv = *(const float4*)&bw[tid * 4];
    float ox = (v.x - mu) * rs * gv.x + bv.x;
    float oy = (v.y - mu) * rs * gv.y + bv.y;
    float oz = (v.z - mu) * rs * gv.z + bv.z;
    float ow = (v.w - mu) * rs * gv.w + bv.w;

    size_t base = (size_t)row * DMODEL + tid * 4;
    *(uint32_t*)&Y[base]     = pack_f16x2(ox, oy);
    *(uint32_t*)&Y[base + 2] = pack_f16x2(oz, ow);
}

// ---------------- merged prologue: all weight transposes + bias concat + T5 table ----------------
#define PREP_BLOCKS (12288 + 256 + 12)

__global__ __launch_bounds__(256)
void prep_kernel(const float* __restrict__ wq, const float* __restrict__ wk,
                 const float* __restrict__ wv, const float* __restrict__ wo,
                 const float* __restrict__ w1, const float* __restrict__ w2,
                 const float* __restrict__ bq, const float* __restrict__ bk,
                 const float* __restrict__ bv, const float* __restrict__ rel_emb)
{
    const int blk = blockIdx.x;
    const int tid = threadIdx.x;

    if (blk < 12288) {
        const float* W; __half* Bh; int K, N, base;
        if (blk < 4096) {
            K = DMODEL; N = DMODEL;
            if (blk < 1024)      { W = wq; Bh = g_wqkv;                   base = 0; }
            else if (blk < 2048) { W = wk; Bh = g_wqkv + DMODEL*DMODEL;   base = 1024; }
            else if (blk < 3072) { W = wv; Bh = g_wqkv + 2*DMODEL*DMODEL; base = 2048; }
            else                 { W = wo; Bh = g_wo;                     base = 3072; }
        } else if (blk < 8192) { W = w1; Bh = g_w1; K = DMODEL; N = DFF;    base = 4096; }
        else                   { W = w2; Bh = g_w2; K = DFF;    N = DMODEL; base = 8192; }
        int t = blk - base;
        int tiles_x = N >> 5;
        int n0 = (t % tiles_x) << 5, k0 = (t / tiles_x) << 5;
        __shared__ float tsm[32][33];
        int tx = tid & 31, ty = tid >> 5;
        #pragma unroll
        for (int i = 0; i < 32; i += 8)
            tsm[ty + i][tx] = W[(size_t)(k0 + ty + i) * N + n0 + tx];
        __syncthreads();
        #pragma unroll
        for (int i = 0; i < 32; i += 8)
            Bh[(size_t)(n0 + ty + i) * K + k0 + tx] = __float2half(tsm[tx][ty + i]);
    } else if (blk < 12288 + 256) {
        int idx = (blk - 12288) * 256 + tid;   // 0 .. 65535
        int h = idx >> 12;
        int t = idx & 4095;
        int rp = t - 2047;
        int n  = -rp;
        int ret = (n < 0) ? 16 : 0;
        int a = n < 0 ? -n : n;
        int bkt;
        if (a < 8) {
            bkt = a;
        } else {
            int vv = 8 + (int)(logf((float)a * 0.125f) / 2.7725887f * 8.0f);
            bkt = vv < 15 ? vv : 15;
        }
        g_bias_tab[idx] = rel_emb[(ret + bkt) * NHEADS + h] * 1.4426950408889634f;
    } else {
        int i = (blk - 12544) * 256 + tid;
        if (i < DMODEL) g_bqkv[i] = bq[i];
        else if (i < 2 * DMODEL) g_bqkv[i] = bk[i - DMODEL];
        else if (i < 3 * DMODEL) g_bqkv[i] = bv[i - 2 * DMODEL];
    }
}

// ================= fp16 warp-MMA GEMM (3-stage cp.async pipeline, BK=64) =================
#define BM 128
#define BN 128
#define BK 64
#define ROWB 144         // 128B data + 16B pad: conflict-free for ldmatrix
#define STG 3
#define GEMM_SMEM (STG * (BM + BN) * ROWB)   // 110592 bytes

template<int EPI>
__global__ __launch_bounds__(256, 2)
void mma_gemm(const __half* __restrict__ A, const __half* __restrict__ B,
              const float* __restrict__ bias, const float* __restrict__ Res,
              float* __restrict__ Cf, __half* __restrict__ Ch,
              int M, int N, int K)
{
    extern __shared__ __align__(16) char gsm[];
    char* sA = gsm;
    char* sB = gsm + STG * BM * ROWB;

    const int tid  = threadIdx.x;
    const int lane = tid & 31;
    const int wid  = tid >> 5;
    const int warp_m = wid & 1;
    const int warp_n = wid >> 1;
    const int rowbase = blockIdx.y * BM;
    const int colbase = blockIdx.x * BN;

    float acc[4][4][4];
    #pragma unroll
    for (int i = 0; i < 4; i++)
        #pragma unroll
        for (int j = 0; j < 4; j++)
            #pragma unroll
            for (int e = 0; e < 4; e++) acc[i][j][e] = 0.f;

    const int C = K / BK;

    auto issue_load = [&](int buf, int c) {
        const int kk = c * BK;
        uint32_t a0 = smem_u32(sA + buf * BM * ROWB);
        uint32_t b0 = smem_u32(sB + buf * BN * ROWB);
        #pragma unroll
        for (int i = 0; i < 4; i++) {
            int idx = i * 256 + tid;
            int r = idx >> 3, cc = idx & 7;
            cp_async16(a0 + r * ROWB + cc * 16,
                       A + (size_t)(rowbase + r) * K + kk + cc * 8);
            cp_async16(b0 + r * ROWB + cc * 16,
                       B + (size_t)(colbase + r) * K + kk + cc * 8);
        }
        cp_commit();
    };

    issue_load(0, 0);
    issue_load(1, 1);

    for (int c = 0; c < C; c++) {
        const int buf = c % STG;
        cp_wait<1>();
        __syncthreads();
        if (c + 2 < C) issue_load((c + 2) % STG, c + 2);

        uint32_t aBase = smem_u32(sA + buf * BM * ROWB);
        uint32_t bBase = smem_u32(sB + buf * BN * ROWB);
        #pragma unroll
        for (int ks = 0; ks < 4; ks++) {
            uint32_t afrag[4][4];
            #pragma unroll
            for (int mt = 0; mt < 4; mt++) {
                uint32_t addr = aBase
                    + (warp_m * 64 + mt * 16 + (lane & 15)) * ROWB
                    + ks * 32 + ((lane >> 4) << 4);
                ldsm_x4(afrag[mt], addr);
            }
            uint32_t bfrag[2][4];
            #pragma unroll
            for (int np = 0; np < 2; np++) {
                uint32_t addr = bBase
                    + (warp_n * 32 + np * 16 + (lane & 15)) * ROWB
                    + ks * 32 + ((lane >> 4) << 4);
                ldsm_x4(bfrag[np], addr);
            }
            #pragma unroll
            for (int mt = 0; mt < 4; mt++)
                #pragma unroll
                for (int nt = 0; nt < 4; nt++) {
                    int np = nt >> 1;
                    uint32_t bb0 = (nt & 1) ? bfrag[np][1] : bfrag[np][0];
                    uint32_t bb1 = (nt & 1) ? bfrag[np][3] : bfrag[np][2];
                    mma16816(acc[mt][nt], afrag[mt], bb0, bb1);
                }
        }
    }

    // ---- epilogue ----
    #pragma unroll
    for (int mt = 0; mt < 4; mt++) {
        #pragma unroll
        for (int nt = 0; nt < 4; nt++) {
            int row0 = rowbase + warp_m * 64 + mt * 16 + (lane >> 2);
            int col  = colbase + warp_n * 32 + nt * 8 + (lane & 3) * 2;
            float2 bv = *(const float2*)&bias[col];
            #pragma unroll
            for (int half = 0; half < 2; half++) {
                int row = row0 + half * 8;
                float cx = acc[mt][nt][half * 2 + 0] + bv.x;
                float cy = acc[mt][nt][half * 2 + 1] + bv.y;
                if (EPI == 1) {
                    cx = fmaxf(cx, 0.f); cy = fmaxf(cy, 0.f);
                    *(uint32_t*)&Ch[(size_t)row * N + col] = pack_f16x2(cx, cy);
                } else if (EPI == 3) {
                    *(uint32_t*)&Ch[(size_t)row * N + col] = pack_f16x2(cx, cy);
                } else {
                    float2 rv = *(const float2*)&Res[(size_t)row * N + col];
                    cx += rv.x; cy += rv.y;
                    float2 o; o.x = cx; o.y = cy;
                    *(float2*)&Cf[(size_t)row * N + col] = o;
                }
            }
        }
    }
}

// ---------------- Flash attention, HMMA fp16, 2-stage K/V ring, fp16 O-acc ----------------
// 128 q rows/CTA, 8 warps x 16 rows; K/V tiles of 64. One __syncthreads per k-tile;
// row-sum l via tensor-pipe MMA against ones; PV accumulated in fp16 (m16n8k16.f16).
#define FROWB 144
#define FQ_OFF    0
#define FK_OFF    (128 * FROWB)               // 18432; 2 stages x 9216
#define FV_OFF    (FK_OFF + 2 * 64 * FROWB)   // 36864
#define FBIAS_OFF (FV_OFF + 2 * 64 * FROWB)   // 55296; 2176 floats
#define FL_SMEM   (FBIAS_OFF + 2176 * 4)      // 64000 bytes -> 3 CTAs/SM

__global__ __launch_bounds__(256, 3)
void flash_mma(const __half* __restrict__ QKV, const float* __restrict__ biasTab,
               __half* __restrict__ Octx)
{
    extern __shared__ __align__(16) char fsm[];
    float* s_bias = (float*)(fsm + FBIAS_OFF);

    const int tid  = threadIdx.x;
    const int lane = tid & 31, warp = tid >> 5;
    const int h = blockIdx.y, b = blockIdx.z;
    const int qbase = blockIdx.x * 128;
    const __half* Qp = QKV + (size_t)b * SEQ * NQKV + h * HEADDIM;
    const __half* Kp = Qp + DMODEL;
    const __half* Vp = Qp + 2 * DMODEL;
    const float* btabq = biasTab + h * 4096 + 1920 - qbase;

    const uint32_t qS = smem_u32(fsm + FQ_OFF);
    const uint32_t kS = smem_u32(fsm + FK_OFF);
    const uint32_t vS = smem_u32(fsm + FV_OFF);

    auto load_kv = [&](int stage, int kt) {
        uint32_t kd = kS + stage * 64 * FROWB;
        uint32_t vd = vS + stage * 64 * FROWB;
        #pragma unroll
        for (int i = 0; i < 2; i++) {
            int idx = i * 256 + tid;
            int r = idx >> 3, c = idx & 7;
            cp_async16(kd + r * FROWB + c * 16,
                       Kp + (size_t)(kt + r) * NQKV + c * 8);
            cp_async16(vd + r * FROWB + c * 16,
                       Vp + (size_t)(kt + r) * NQKV + c * 8);
        }
        cp_commit();
    };

    // prologue: q tile (group 0), kv stage 0 (group 1), bias strip
    #pragma unroll
    for (int i = 0; i < 4; i++) {
        int idx = i * 256 + tid;
        int r = idx >> 3, c = idx & 7;
        cp_async16(qS + r * FROWB + c * 16,
                   Qp + (size_t)(qbase + r) * NQKV + c * 8);
    }
    cp_commit();
    load_kv(0, 0);
    for (int i = tid; i < 2176; i += 256) s_bias[i] = btabq[i];

    uint32_t acc_h[8][2];
    #pragma unroll
    for (int i = 0; i < 8; i++) { acc_h[i][0] = 0u; acc_h[i][1] = 0u; }
    float acc_l[4] = {0.f, 0.f, 0.f, 0.f};
    uint32_t a_q[4][4];
    const uint32_t ONES = 0x3C003C00u;          // fp16 {1.0, 1.0}

    const int base0 = 127 + 2 * (lane & 3) - (warp * 16 + (lane >> 2));
    const float SCL2 = 0.125f * 1.4426950408889634f;
    const int NIT = SEQ / 64;

    for (int it = 0; it < NIT; it++) {
        const int kt = it * 64;
        const int stage = it & 1;
        __syncthreads();       // all warps done with stage^1 (read in iter it-1)
        if (it + 1 < NIT) load_kv(stage ^ 1, kt + 64);
        else cp_commit();      // keep group counting uniform
        cp_wait<1>();          // kv(it) (and q, on it=0) arrived
        __syncthreads();

        if (it == 0) {
            #pragma unroll
            for (int ks = 0; ks < 4; ks++)
                ldsm_x4(a_q[ks], qS + (warp * 16 + (lane & 15)) * FROWB
                                   + ks * 32 + ((lane >> 4) << 4));
        }

        const uint32_t kB = kS + stage * 64 * FROWB;
        const uint32_t vB = vS + stage * 64 * FROWB;

        // ---- S = Q K^T ----
        float accs[8][4];
        #pragma unroll
        for (int i = 0; i < 8; i++)
            #pragma unroll
            for (int e = 0; e < 4; e++) accs[i][e] = 0.f;

        #pragma unroll
        for (int ks = 0; ks < 4; ks++) {
            #pragma unroll
            for (int np = 0; np < 4; np++) {
                uint32_t bb[4];
                uint32_t addr = kB
                    + (np * 16 + (lane & 7) + ((lane >> 4) << 3)) * FROWB
                    + ks * 32 + (((lane >> 3) & 1) << 4);
                ldsm_x4(bb, addr);
                mma16816(accs[2 * np],     a_q[ks], bb[0], bb[1]);
                mma16816(accs[2 * np + 1], a_q[ks], bb[2], bb[3]);
            }
        }

        // ---- p = 2^(score*log2e + bias'), straight to fp16 fragments ----
        uint32_t p2[8][2];
        #pragma unroll
        for (int nt = 0; nt < 8; nt++) {
            int j0 = kt + base0 + nt * 8;
            float v0 = fmaf(accs[nt][0], SCL2, s_bias[j0]);
            float v1 = fmaf(accs[nt][1], SCL2, s_bias[j0 + 1]);
            float v2 = fmaf(accs[nt][2], SCL2, s_bias[j0 - 8]);
            float v3 = fmaf(accs[nt][3], SCL2, s_bias[j0 - 7]);
            p2[nt][0] = ex2_f16x2(cvt_f16x2(v0, v1));
            p2[nt][1] = ex2_f16x2(cvt_f16x2(v2, v3));
        }

        // ---- O += P V (fp16 acc);  l += P @ ones (fp32 acc, tensor pipe) ----
        #pragma unroll
        for (int ks = 0; ks < 4; ks++) {
            uint32_t aP[4];
            aP[0] = p2[2 * ks][0];
            aP[1] = p2[2 * ks][1];
            aP[2] = p2[2 * ks + 1][0];
            aP[3] = p2[2 * ks + 1][1];
            mma16816(acc_l, aP, ONES, ONES);
            #pragma unroll
            for (int dp = 0; dp < 4; dp++) {
                uint32_t bb[4];
                uint32_t addr = vB
                    + (ks * 16 + (lane & 7) + (((lane >> 3) & 1) << 3)) * FROWB
                    + dp * 32 + ((lane >> 4) << 4);
                ldsm_x4_t(bb, addr);
                mma16816_h(acc_h[2 * dp],     aP, bb[0], bb[1]);
                mma16816_h(acc_h[2 * dp + 1], aP, bb[2], bb[3]);
            }
        }
    }

    // acc_l[0] = full row sum for row0, acc_l[2] for row1 (all columns identical)
    __half2 hv0 = __float2half2_rn(1.0f / acc_l[0]);
    __half2 hv1 = __float2half2_rn(1.0f / acc_l[2]);
    uint32_t inv0 = *reinterpret_cast<uint32_t*>(&hv0);
    uint32_t inv1 = *reinterpret_cast<uint32_t*>(&hv1);
    int row0 = qbase + warp * 16 + (lane >> 2);
    int row1 = row0 + 8;
    #pragma unroll
    for (int dt = 0; dt < 8; dt++) {
        int col = h * HEADDIM + dt * 8 + 2 * (lane & 3);
        *(uint32_t*)&Octx[((size_t)b * SEQ + row0) * DMODEL + col] =
            hmul2_u32(acc_h[dt][0], inv0);
        *(uint32_t*)&Octx[((size_t)b * SEQ + row1) * DMODEL + col] =
            hmul2_u32(acc_h[dt][1], inv1);
    }
}

// ---------------- host launcher ----------------
extern "C" void kernel_launch(void* const* d_in, const int* in_sizes, int n_in,
                              void* d_out, int out_size)
{
    (void)in_sizes; (void)n_in; (void)out_size;
    const float* src   = (const float*)d_in[0];
    const float* wq    = (const float*)d_in[1];
    const float* bq    = (const float*)d_in[2];
    const float* wk    = (const float*)d_in[3];
    const float* bk    = (const float*)d_in[4];
    const float* wv    = (const float*)d_in[5];
    const float* bv    = (const float*)d_in[6];
    const float* wo    = (const float*)d_in[7];
    const float* bo    = (const float*)d_in[8];
    const float* w1    = (const float*)d_in[9];
    const float* b1    = (const float*)d_in[10];
    const float* w2    = (const float*)d_in[11];
    const float* b2    = (const float*)d_in[12];
    const float* ln1g  = (const float*)d_in[13];
    const float* ln1b  = (const float*)d_in[14];
    const float* ln2g  = (const float*)d_in[15];
    const float* ln2b  = (const float*)d_in[16];
    const float* rele  = (const float*)d_in[17];
    float* out = (float*)d_out;

    __half *xn, *qkv, *ctx, *yn, *h1, *wqkv, *woh, *w1h, *w2h;
    float *x, *btab, *bqkv;
    cudaGetSymbolAddress((void**)&xn, g_xn);
    cudaGetSymbolAddress((void**)&qkv, g_qkv);
    cudaGetSymbolAddress((void**)&ctx, g_ctx);
    cudaGetSymbolAddress((void**)&x, g_x);
    cudaGetSymbolAddress((void**)&yn, g_yn);
    cudaGetSymbolAddress((void**)&h1, g_h1);
    cudaGetSymbolAddress((void**)&wqkv, g_wqkv);
    cudaGetSymbolAddress((void**)&woh, g_wo);
    cudaGetSymbolAddress((void**)&w1h, g_w1);
    cudaGetSymbolAddress((void**)&w2h, g_w2);
    cudaGetSymbolAddress((void**)&btab, g_bias_tab);
    cudaGetSymbolAddress((void**)&bqkv, g_bqkv);

    cudaFuncSetAttribute(mma_gemm<1>, cudaFuncAttributeMaxDynamicSharedMemorySize, GEMM_SMEM);
    cudaFuncSetAttribute(mma_gemm<2>, cudaFuncAttributeMaxDynamicSharedMemorySize, GEMM_SMEM);
    cudaFuncSetAttribute(mma_gemm<3>, cudaFuncAttributeMaxDynamicSharedMemorySize, GEMM_SMEM);
    cudaFuncSetAttribute(flash_mma, cudaFuncAttributeMaxDynamicSharedMemorySize, FL_SMEM);

    // 1) merged prologue: weight transposes + qkv bias concat + T5 table
    prep_kernel<<<PREP_BLOCKS, 256>>>(wq, wk, wv, wo, w1, w2, bq, bk, bv, rele);
    // 2) pre-norm
    ln_kernel<<<MTOK, 256>>>(src, ln1g, ln1b, xn);
    // 3) fused QKV projection -> fp16
    mma_gemm<3><<<dim3(NQKV/128, MTOK/128), 256, GEMM_SMEM>>>(
        xn, wqkv, bqkv, nullptr, nullptr, qkv, MTOK, NQKV, DMODEL);
    // 4) attention (HMMA fp16, 2-stage ring, fp16 O-acc, 3 CTAs/SM)
    flash_mma<<<dim3(SEQ/128, NHEADS, BATCH), 256, FL_SMEM>>>(qkv, btab, ctx);
    // 5) output projection + residual
    mma_gemm<2><<<dim3(DMODEL/128, MTOK/128), 256, GEMM_SMEM>>>(
        ctx, woh, bo, src, x, nullptr, MTOK, DMODEL, DMODEL);
    // 6) FFN pre-norm
    ln_kernel<<<MTOK, 256>>>(x, ln2g, ln2b, yn);
    // 7) FFN
    mma_gemm<1><<<dim3(DFF/128, MTOK/128), 256, GEMM_SMEM>>>(
        yn, w1h, b1, nullptr, nullptr, h1, MTOK, DFF, DMODEL);
    mma_gemm<2><<<dim3(DMODEL/128, MTOK/128), 256, GEMM_SMEM>>>(
        h1, w2h, b2, x, out, nullptr, MTOK, DMODEL, DFF);
}

// round 16
// speedup vs baseline: 1.0085x; 1.0085x over previous
#include <cuda_runtime.h>
#include <cuda_fp16.h>
#include <cstdint>
#include <cmath>

// ---------------- problem constants ----------------
#define BATCH   4
#define SEQ     2048
#define DMODEL  1024
#define NHEADS  16
#define HEADDIM 64
#define DFF     4096
#define MTOK    (BATCH*SEQ)          // 8192 rows
#define NQKV    (3*DMODEL)           // fused QKV width

// ---------------- scratch (device globals, no runtime alloc) ----------------
__device__ __align__(256) __half g_xn [MTOK*DMODEL];
__device__ __align__(256) __half g_qkv[MTOK*NQKV];       // [row][q|k|v]
__device__ __align__(256) __half g_ctx[MTOK*DMODEL];
__device__ __align__(256) float  g_x  [MTOK*DMODEL];
__device__ __align__(256) __half g_yn [MTOK*DMODEL];
__device__ __align__(256) __half g_h1 [MTOK*DFF];
// transposed weights: [N,K] K-major, fp16
__device__ __align__(256) __half g_wqkv[NQKV*DMODEL];
__device__ __align__(256) __half g_wo[DMODEL*DMODEL];
__device__ __align__(256) __half g_w1[DMODEL*DFF];
__device__ __align__(256) __half g_w2[DFF*DMODEL];
__device__ float g_bqkv[NQKV];
__device__ float g_bias_tab[NHEADS*4096];   // [h][ (k-q)+2047 ], pre-scaled by log2(e)

// ================= warp-MMA helpers (sm_80+ PTX) =================
__device__ __forceinline__ uint32_t smem_u32(const void* p) {
    return (uint32_t)__cvta_generic_to_shared(p);
}
__device__ __forceinline__ void cp_async16(uint32_t dst, const void* src) {
    asm volatile("cp.async.cg.shared.global [%0], [%1], 16;" :: "r"(dst), "l"(src));
}
__device__ __forceinline__ void cp_commit() {
    asm volatile("cp.async.commit_group;");
}
template<int N>
__device__ __forceinline__ void cp_wait() {
    asm volatile("cp.async.wait_group %0;" :: "n"(N));
}
__device__ __forceinline__ void ldsm_x4(uint32_t (&r)[4], uint32_t addr) {
    asm volatile("ldmatrix.sync.aligned.m8n8.x4.shared.b16 {%0,%1,%2,%3}, [%4];"
                 : "=r"(r[0]), "=r"(r[1]), "=r"(r[2]), "=r"(r[3]) : "r"(addr));
}
__device__ __forceinline__ void ldsm_x4_t(uint32_t (&r)[4], uint32_t addr) {
    asm volatile("ldmatrix.sync.aligned.m8n8.x4.trans.shared.b16 {%0,%1,%2,%3}, [%4];"
                 : "=r"(r[0]), "=r"(r[1]), "=r"(r[2]), "=r"(r[3]) : "r"(addr));
}
__device__ __forceinline__ void mma16816(float (&d)[4], const uint32_t (&a)[4],
                                         uint32_t b0, uint32_t b1) {
    asm volatile(
        "mma.sync.aligned.m16n8k16.row.col.f32.f16.f16.f32 "
        "{%0,%1,%2,%3}, {%4,%5,%6,%7}, {%8,%9}, {%0,%1,%2,%3};"
        : "+f"(d[0]), "+f"(d[1]), "+f"(d[2]), "+f"(d[3])
        : "r"(a[0]), "r"(a[1]), "r"(a[2]), "r"(a[3]), "r"(b0), "r"(b1));
}
// fp16-accumulator variant: d0 = {row, col:col+1}, d1 = {row+8, col:col+1}
__device__ __forceinline__ void mma16816_h(uint32_t (&d)[2], const uint32_t (&a)[4],
                                           uint32_t b0, uint32_t b1) {
    asm volatile(
        "mma.sync.aligned.m16n8k16.row.col.f16.f16.f16.f16 "
        "{%0,%1}, {%2,%3,%4,%5}, {%6,%7}, {%0,%1};"
        : "+r"(d[0]), "+r"(d[1])
        : "r"(a[0]), "r"(a[1]), "r"(a[2]), "r"(a[3]), "r"(b0), "r"(b1));
}
__device__ __forceinline__ uint32_t pack_f16x2(float lo, float hi) {
    __half2 t;
    t.x = __float2half(lo);
    t.y = __float2half(hi);
    return *reinterpret_cast<uint32_t*>(&t);
}
// cvt.rn.f16x2.f32 d, hi, lo  -> low half = lo
__device__ __forceinline__ uint32_t cvt_f16x2(float lo, float hi) {
    uint32_t d;
    asm("cvt.rn.f16x2.f32 %0, %1, %2;" : "=r"(d) : "f"(hi), "f"(lo));
    return d;
}
__device__ __forceinline__ uint32_t ex2_f16x2(uint32_t x) {
    uint32_t d;
    asm("ex2.approx.f16x2 %0, %1;" : "=r"(d) : "r"(x));
    return d;
}
__device__ __forceinline__ uint32_t hmul2_u32(uint32_t a, uint32_t b) {
    uint32_t d;
    asm("mul.f16x2 %0, %1, %2;" : "=r"(d) : "r"(a), "r"(b));
    return d;
}

// ---------------- LayerNorm body (shared by ln_kernel and prep fusion) ----------------
__device__ __forceinline__ void ln_row(const float* __restrict__ X,
                                       const float* __restrict__ gw,
                                       const float* __restrict__ bw,
                                       __half* __restrict__ Y,
                                       int row, int tid, float* red /*[16]*/)
{
    const int lane = tid & 31, warp = tid >> 5;
    const float* xr = X + (size_t)row * DMODEL;

    float4 v = *(const float4*)&xr[tid * 4];
    float s  = v.x + v.y + v.z + v.w;
    float sq = fmaf(v.x, v.x, fmaf(v.y, v.y, fmaf(v.z, v.z, v.w * v.w)));
    #pragma unroll
    for (int o = 16; o; o >>= 1) {
        s  += __shfl_xor_sync(0xffffffffu, s,  o);
        sq += __shfl_xor_sync(0xffffffffu, sq, o);
    }
    if (lane == 0) { red[warp * 2] = s; red[warp * 2 + 1] = sq; }
    __syncthreads();
    float S = 0.f, SQ = 0.f;
    #pragma unroll
    for (int i = 0; i < 8; i++) { S += red[i * 2]; SQ += red[i * 2 + 1]; }
    float mu  = S * (1.0f / DMODEL);
    float var = SQ * (1.0f / DMODEL) - mu * mu;
    float rs  = rsqrtf(var + 1e-6f);

    float4 gv = *(const float4*)&gw[tid * 4];
    float4 bv = *(const float4*)&bw[tid * 4];
    float ox = (v.x - mu) * rs * gv.x + bv.x;
    float oy = (v.y - mu) * rs * gv.y + bv.y;
    float oz = (v.z - mu) * rs * gv.z + bv.z;
    float ow = (v.w - mu) * rs * gv.w + bv.w;

    size_t base = (size_t)row * DMODEL + tid * 4;
    *(uint32_t*)&Y[base]     = pack_f16x2(ox, oy);
    *(uint32_t*)&Y[base + 2] = pack_f16x2(oz, ow);
}

__global__ __launch_bounds__(256)
void ln_kernel(const float* __restrict__ X, const float* __restrict__ gw,
               const float* __restrict__ bw, __half* __restrict__ Y)
{
    __shared__ float red[16];
    ln_row(X, gw, bw, Y, blockIdx.x, threadIdx.x, red);
}

// ---------------- merged prologue: weight transposes + bias concat + T5 table + ln1 ----------------
// blocks [0,12288): 32x32 transpose tiles; [12288,12544): T5 table;
// [12544,12556): qkv bias concat; [12556,12556+8192): ln1 rows.
#define PREP_BLOCKS (12288 + 256 + 12 + MTOK)

__global__ __launch_bounds__(256)
void prep_kernel(const float* __restrict__ wq, const float* __restrict__ wk,
                 const float* __restrict__ wv, const float* __restrict__ wo,
                 const float* __restrict__ w1, const float* __restrict__ w2,
                 const float* __restrict__ bq, const float* __restrict__ bk,
                 const float* __restrict__ bv, const float* __restrict__ rel_emb,
                 const float* __restrict__ src, const float* __restrict__ ln1g,
                 const float* __restrict__ ln1b)
{
    const int blk = blockIdx.x;
    const int tid = threadIdx.x;
    __shared__ float tsm[32][33];

    if (blk < 12288) {
        const float* W; __half* Bh; int K, N, base;
        if (blk < 4096) {
            K = DMODEL; N = DMODEL;
            if (blk < 1024)      { W = wq; Bh = g_wqkv;                   base = 0; }
            else if (blk < 2048) { W = wk; Bh = g_wqkv + DMODEL*DMODEL;   base = 1024; }
            else if (blk < 3072) { W = wv; Bh = g_wqkv + 2*DMODEL*DMODEL; base = 2048; }
            else                 { W = wo; Bh = g_wo;                     base = 3072; }
        } else if (blk < 8192) { W = w1; Bh = g_w1; K = DMODEL; N = DFF;    base = 4096; }
        else                   { W = w2; Bh = g_w2; K = DFF;    N = DMODEL; base = 8192; }
        int t = blk - base;
        int tiles_x = N >> 5;
        int n0 = (t % tiles_x) << 5, k0 = (t / tiles_x) << 5;
        int tx = tid & 31, ty = tid >> 5;
        #pragma unroll
        for (int i = 0; i < 32; i += 8)
            tsm[ty + i][tx] = W[(size_t)(k0 + ty + i) * N + n0 + tx];
        __syncthreads();
        #pragma unroll
        for (int i = 0; i < 32; i += 8)
            Bh[(size_t)(n0 + ty + i) * K + k0 + tx] = __float2half(tsm[tx][ty + i]);
    } else if (blk < 12288 + 256) {
        int idx = (blk - 12288) * 256 + tid;   // 0 .. 65535
        int h = idx >> 12;
        int t = idx & 4095;
        int rp = t - 2047;
        int n  = -rp;
        int ret = (n < 0) ? 16 : 0;
        int a = n < 0 ? -n : n;
        int bkt;
        if (a < 8) {
            bkt = a;
        } else {
            int vv = 8 + (int)(logf((float)a * 0.125f) / 2.7725887f * 8.0f);
            bkt = vv < 15 ? vv : 15;
        }
        g_bias_tab[idx] = rel_emb[(ret + bkt) * NHEADS + h] * 1.4426950408889634f;
    } else if (blk < 12556) {
        int i = (blk - 12544) * 256 + tid;
        if (i < DMODEL) g_bqkv[i] = bq[i];
        else if (i < 2 * DMODEL) g_bqkv[i] = bk[i - DMODEL];
        else if (i < 3 * DMODEL) g_bqkv[i] = bv[i - 2 * DMODEL];
    } else {
        ln_row(src, ln1g, ln1b, g_xn, blk - 12556, tid, &tsm[0][0]);
    }
}

// ================= fp16 warp-MMA GEMM (3-stage cp.async pipeline, BK=64) =================
#define BM 128
#define BN 128
#define BK 64
#define ROWB 144         // 128B data + 16B pad: conflict-free for ldmatrix
#define STG 3
#define GEMM_SMEM (STG * (BM + BN) * ROWB)   // 110592 bytes

template<int EPI>
__global__ __launch_bounds__(256, 2)
void mma_gemm(const __half* __restrict__ A, const __half* __restrict__ B,
              const float* __restrict__ bias, const float* __restrict__ Res,
              float* __restrict__ Cf, __half* __restrict__ Ch,
              int M, int N, int K)
{
    extern __shared__ __align__(16) char gsm[];
    char* sA = gsm;
    char* sB = gsm + STG * BM * ROWB;

    const int tid  = threadIdx.x;
    const int lane = tid & 31;
    const int wid  = tid >> 5;
    const int warp_m = wid & 1;
    const int warp_n = wid >> 1;
    const int rowbase = blockIdx.y * BM;
    const int colbase = blockIdx.x * BN;

    float acc[4][4][4];
    #pragma unroll
    for (int i = 0; i < 4; i++)
        #pragma unroll
        for (int j = 0; j < 4; j++)
            #pragma unroll
            for (int e = 0; e < 4; e++) acc[i][j][e] = 0.f;

    const int C = K / BK;

    auto issue_load = [&](int buf, int c) {
        const int kk = c * BK;
        uint32_t a0 = smem_u32(sA + buf * BM * ROWB);
        uint32_t b0 = smem_u32(sB + buf * BN * ROWB);
        #pragma unroll
        for (int i = 0; i < 4; i++) {
            int idx = i * 256 + tid;
            int r = idx >> 3, cc = idx & 7;
            cp_async16(a0 + r * ROWB + cc * 16,
                       A + (size_t)(rowbase + r) * K + kk + cc * 8);
            cp_async16(b0 + r * ROWB + cc * 16,
                       B + (size_t)(colbase + r) * K + kk + cc * 8);
        }
        cp_commit();
    };

    issue_load(0, 0);
    issue_load(1, 1);

    for (int c = 0; c < C; c++) {
        const int buf = c % STG;
        cp_wait<1>();
        __syncthreads();
        if (c + 2 < C) issue_load((c + 2) % STG, c + 2);

        uint32_t aBase = smem_u32(sA + buf * BM * ROWB);
        uint32_t bBase = smem_u32(sB + buf * BN * ROWB);
        #pragma unroll
        for (int ks = 0; ks < 4; ks++) {
            uint32_t afrag[4][4];
            #pragma unroll
            for (int mt = 0; mt < 4; mt++) {
                uint32_t addr = aBase
                    + (warp_m * 64 + mt * 16 + (lane & 15)) * ROWB
                    + ks * 32 + ((lane >> 4) << 4);
                ldsm_x4(afrag[mt], addr);
            }
            uint32_t bfrag[2][4];
            #pragma unroll
            for (int np = 0; np < 2; np++) {
                uint32_t addr = bBase
                    + (warp_n * 32 + np * 16 + (lane & 15)) * ROWB
                    + ks * 32 + ((lane >> 4) << 4);
                ldsm_x4(bfrag[np], addr);
            }
            #pragma unroll
            for (int mt = 0; mt < 4; mt++)
                #pragma unroll
                for (int nt = 0; nt < 4; nt++) {
                    int np = nt >> 1;
                    uint32_t bb0 = (nt & 1) ? bfrag[np][1] : bfrag[np][0];
                    uint32_t bb1 = (nt & 1) ? bfrag[np][3] : bfrag[np][2];
                    mma16816(acc[mt][nt], afrag[mt], bb0, bb1);
                }
        }
    }

    // ---- epilogue ----
    #pragma unroll
    for (int mt = 0; mt < 4; mt++) {
        #pragma unroll
        for (int nt = 0; nt < 4; nt++) {
            int row0 = rowbase + warp_m * 64 + mt * 16 + (lane >> 2);
            int col  = colbase + warp_n * 32 + nt * 8 + (lane & 3) * 2;
            float2 bv = *(const float2*)&bias[col];
            #pragma unroll
            for (int half = 0; half < 2; half++) {
                int row = row0 + half * 8;
                float cx = acc[mt][nt][half * 2 + 0] + bv.x;
                float cy = acc[mt][nt][half * 2 + 1] + bv.y;
                if (EPI == 1) {
                    cx = fmaxf(cx, 0.f); cy = fmaxf(cy, 0.f);
                    *(uint32_t*)&Ch[(size_t)row * N + col] = pack_f16x2(cx, cy);
                } else if (EPI == 3) {
                    *(uint32_t*)&Ch[(size_t)row * N + col] = pack_f16x2(cx, cy);
                } else {
                    float2 rv = *(const float2*)&Res[(size_t)row * N + col];
                    cx += rv.x; cy += rv.y;
                    float2 o; o.x = cx; o.y = cy;
                    *(float2*)&Cf[(size_t)row * N + col] = o;
                }
            }
        }
    }
}

// ---------------- Flash attention (R14 structure + fp16 O-acc) ----------------
// 3-stage K/V ring, one __syncthreads per k-tile, Q fragments hoisted, bias strip
// preloaded, row-sum l via tensor-pipe MMA, PV accumulated in fp16.
#define FROWB 144
#define FQ_OFF    0
#define FK_OFF    (128 * FROWB)               // 18432; 3 stages x 9216
#define FV_OFF    (FK_OFF + 3 * 64 * FROWB)   // 46080
#define FBIAS_OFF (FV_OFF + 3 * 64 * FROWB)   // 73728; 2176 floats
#define FL_SMEM   (FBIAS_OFF + 2176 * 4)      // 82432 bytes

__global__ __launch_bounds__(256)
void flash_mma(const __half* __restrict__ QKV, const float* __restrict__ biasTab,
               __half* __restrict__ Octx)
{
    extern __shared__ __align__(16) char fsm[];
    float* s_bias = (float*)(fsm + FBIAS_OFF);

    const int tid  = threadIdx.x;
    const int lane = tid & 31, warp = tid >> 5;
    const int h = blockIdx.y, b = blockIdx.z;
    const int qbase = blockIdx.x * 128;
    const __half* Qp = QKV + (size_t)b * SEQ * NQKV + h * HEADDIM;
    const __half* Kp = Qp + DMODEL;
    const __half* Vp = Qp + 2 * DMODEL;
    const float* btabq = biasTab + h * 4096 + 1920 - qbase;

    const uint32_t qS = smem_u32(fsm + FQ_OFF);
    const uint32_t kS = smem_u32(fsm + FK_OFF);
    const uint32_t vS = smem_u32(fsm + FV_OFF);

    auto load_kv = [&](int stage, int kt) {
        uint32_t kd = kS + stage * 64 * FROWB;
        uint32_t vd = vS + stage * 64 * FROWB;
        #pragma unroll
        for (int i = 0; i < 2; i++) {
            int idx = i * 256 + tid;
            int r = idx >> 3, c = idx & 7;
            cp_async16(kd + r * FROWB + c * 16,
                       Kp + (size_t)(kt + r) * NQKV + c * 8);
            cp_async16(vd + r * FROWB + c * 16,
                       Vp + (size_t)(kt + r) * NQKV + c * 8);
        }
        cp_commit();
    };

    // prologue: q tile (group 0), kv stages 0,1 (groups 1,2), bias strip
    #pragma unroll
    for (int i = 0; i < 4; i++) {
        int idx = i * 256 + tid;
        int r = idx >> 3, c = idx & 7;
        cp_async16(qS + r * FROWB + c * 16,
                   Qp + (size_t)(qbase + r) * NQKV + c * 8);
    }
    cp_commit();
    load_kv(0, 0);
    load_kv(1, 64);
    for (int i = tid; i < 2176; i += 256) s_bias[i] = btabq[i];

    uint32_t acc_h[8][2];
    #pragma unroll
    for (int i = 0; i < 8; i++) { acc_h[i][0] = 0u; acc_h[i][1] = 0u; }
    float acc_l[4] = {0.f, 0.f, 0.f, 0.f};
    uint32_t a_q[4][4];
    const uint32_t ONES = 0x3C003C00u;          // fp16 {1.0, 1.0}

    const int base0 = 127 + 2 * (lane & 3) - (warp * 16 + (lane >> 2));
    const float SCL2 = 0.125f * 1.4426950408889634f;
    const int NIT = SEQ / 64;

    for (int it = 0; it < NIT; it++) {
        const int kt = it * 64;
        const int stage = it % 3;
        cp_wait<1>();          // kv(it) (and q, bias on it=0) arrived
        __syncthreads();       // all warps done with this stage buffer's previous use
        if (it + 2 < NIT) load_kv((it + 2) % 3, kt + 128);
        else cp_commit();      // keep group counting uniform

        if (it == 0) {
            #pragma unroll
            for (int ks = 0; ks < 4; ks++)
                ldsm_x4(a_q[ks], qS + (warp * 16 + (lane & 15)) * FROWB
                                   + ks * 32 + ((lane >> 4) << 4));
        }

        const uint32_t kB = kS + stage * 64 * FROWB;
        const uint32_t vB = vS + stage * 64 * FROWB;

        // ---- S = Q K^T ----
        float accs[8][4];
        #pragma unroll
        for (int i = 0; i < 8; i++)
            #pragma unroll
            for (int e = 0; e < 4; e++) accs[i][e] = 0.f;

        #pragma unroll
        for (int ks = 0; ks < 4; ks++) {
            #pragma unroll
            for (int np = 0; np < 4; np++) {
                uint32_t bb[4];
                uint32_t addr = kB
                    + (np * 16 + (lane & 7) + ((lane >> 4) << 3)) * FROWB
                    + ks * 32 + (((lane >> 3) & 1) << 4);
                ldsm_x4(bb, addr);
                mma16816(accs[2 * np],     a_q[ks], bb[0], bb[1]);
                mma16816(accs[2 * np + 1], a_q[ks], bb[2], bb[3]);
            }
        }

        // ---- p = 2^(score*log2e + bias'), straight to fp16 fragments ----
        uint32_t p2[8][2];
        #pragma unroll
        for (int nt = 0; nt < 8; nt++) {
            int j0 = kt + base0 + nt * 8;
            float v0 = fmaf(accs[nt][0], SCL2, s_bias[j0]);
            float v1 = fmaf(accs[nt][1], SCL2, s_bias[j0 + 1]);
            float v2 = fmaf(accs[nt][2], SCL2, s_bias[j0 - 8]);
            float v3 = fmaf(accs[nt][3], SCL2, s_bias[j0 - 7]);
            p2[nt][0] = ex2_f16x2(cvt_f16x2(v0, v1));
            p2[nt][1] = ex2_f16x2(cvt_f16x2(v2, v3));
        }

        // ---- O += P V (fp16 acc);  l += P @ ones (fp32 acc, tensor pipe) ----
        #pragma unroll
        for (int ks = 0; ks < 4; ks++) {
            uint32_t aP[4];
            aP[0] = p2[2 * ks][0];
            aP[1] = p2[2 * ks][1];
            aP[2] = p2[2 * ks + 1][0];
            aP[3] = p2[2 * ks + 1][1];
            mma16816(acc_l, aP, ONES, ONES);
            #pragma unroll
            for (int dp = 0; dp < 4; dp++) {
                uint32_t bb[4];
                uint32_t addr = vB
                    + (ks * 16 + (lane & 7) + (((lane >> 3) & 1) << 3)) * FROWB
                    + dp * 32 + ((lane >> 4) << 4);
                ldsm_x4_t(bb, addr);
                mma16816_h(acc_h[2 * dp],     aP, bb[0], bb[1]);
                mma16816_h(acc_h[2 * dp + 1], aP, bb[2], bb[3]);
            }
        }
    }

    // acc_l[0] = full row sum for row0, acc_l[2] for row1 (all columns identical)
    __half2 hv0 = __float2half2_rn(1.0f / acc_l[0]);
    __half2 hv1 = __float2half2_rn(1.0f / acc_l[2]);
    uint32_t inv0 = *reinterpret_cast<uint32_t*>(&hv0);
    uint32_t inv1 = *reinterpret_cast<uint32_t*>(&hv1);
    int row0 = qbase + warp * 16 + (lane >> 2);
    int row1 = row0 + 8;
    #pragma unroll
    for (int dt = 0; dt < 8; dt++) {
        int col = h * HEADDIM + dt * 8 + 2 * (lane & 3);
        *(uint32_t*)&Octx[((size_t)b * SEQ + row0) * DMODEL + col] =
            hmul2_u32(acc_h[dt][0], inv0);
        *(uint32_t*)&Octx[((size_t)b * SEQ + row1) * DMODEL + col] =
            hmul2_u32(acc_h[dt][1], inv1);
    }
}

// ---------------- host launcher ----------------
extern "C" void kernel_launch(void* const* d_in, const int* in_sizes, int n_in,
                              void* d_out, int out_size)
{
    (void)in_sizes; (void)n_in; (void)out_size;
    const float* src   = (const float*)d_in[0];
    const float* wq    = (const float*)d_in[1];
    const float* bq    = (const float*)d_in[2];
    const float* wk    = (const float*)d_in[3];
    const float* bk    = (const float*)d_in[4];
    const float* wv    = (const float*)d_in[5];
    const float* bv    = (const float*)d_in[6];
    const float* wo    = (const float*)d_in[7];
    const float* bo    = (const float*)d_in[8];
    const float* w1    = (const float*)d_in[9];
    const float* b1    = (const float*)d_in[10];
    const float* w2    = (const float*)d_in[11];
    const float* b2    = (const float*)d_in[12];
    const float* ln1g  = (const float*)d_in[13];
    const float* ln1b  = (const float*)d_in[14];
    const float* ln2g  = (const float*)d_in[15];
    const float* ln2b  = (const float*)d_in[16];
    const float* rele  = (const float*)d_in[17];
    float* out = (float*)d_out;

    __half *xn, *qkv, *ctx, *yn, *h1, *wqkv, *woh, *w1h, *w2h;
    float *x, *btab, *bqkv;
    cudaGetSymbolAddress((void**)&xn, g_xn);
    cudaGetSymbolAddress((void**)&qkv, g_qkv);
    cudaGetSymbolAddress((void**)&ctx, g_ctx);
    cudaGetSymbolAddress((void**)&x, g_x);
    cudaGetSymbolAddress((void**)&yn, g_yn);
    cudaGetSymbolAddress((void**)&h1, g_h1);
    cudaGetSymbolAddress((void**)&wqkv, g_wqkv);
    cudaGetSymbolAddress((void**)&woh, g_wo);
    cudaGetSymbolAddress((void**)&w1h, g_w1);
    cudaGetSymbolAddress((void**)&w2h, g_w2);
    cudaGetSymbolAddress((void**)&btab, g_bias_tab);
    cudaGetSymbolAddress((void**)&bqkv, g_bqkv);

    cudaFuncSetAttribute(mma_gemm<1>, cudaFuncAttributeMaxDynamicSharedMemorySize, GEMM_SMEM);
    cudaFuncSetAttribute(mma_gemm<2>, cudaFuncAttributeMaxDynamicSharedMemorySize, GEMM_SMEM);
    cudaFuncSetAttribute(mma_gemm<3>, cudaFuncAttributeMaxDynamicSharedMemorySize, GEMM_SMEM);
    cudaFuncSetAttribute(flash_mma, cudaFuncAttributeMaxDynamicSharedMemorySize, FL_SMEM);

    // 1) merged prologue: weight transposes + qkv bias concat + T5 table + ln1
    prep_kernel<<<PREP_BLOCKS, 256>>>(wq, wk, wv, wo, w1, w2, bq, bk, bv, rele,
                                      src, ln1g, ln1b);
    // 2) fused QKV projection -> fp16
    mma_gemm<3><<<dim3(NQKV/128, MTOK/128), 256, GEMM_SMEM>>>(
        xn, wqkv, bqkv, nullptr, nullptr, qkv, MTOK, NQKV, DMODEL);
    // 3) attention (HMMA fp16, 3-stage ring, fp16 O-acc)
    flash_mma<<<dim3(SEQ/128, NHEADS, BATCH), 256, FL_SMEM>>>(qkv, btab, ctx);
    // 4) output projection + residual
    mma_gemm<2><<<dim3(DMODEL/128, MTOK/128), 256, GEMM_SMEM>>>(
        ctx, woh, bo, src, x, nullptr, MTOK, DMODEL, DMODEL);
    // 5) FFN pre-norm
    ln_kernel<<<MTOK, 256>>>(x, ln2g, ln2b, yn);
    // 6) FFN
    mma_gemm<1><<<dim3(DFF/128, MTOK/128), 256, GEMM_SMEM>>>(
        yn, w1h, b1, nullptr, nullptr, h1, MTOK, DFF, DMODEL);
    mma_gemm<2><<<dim3(DMODEL/128, MTOK/128), 256, GEMM_SMEM>>>(
        h1, w2h, b2, x, out, nullptr, MTOK, DMODEL, DFF);
}